// round 10
// baseline (speedup 1.0000x reference)
#include <cuda_runtime.h>
#include <cuda_fp16.h>

// Correlation: out[b, di*9+dj, y, x] = (1/64) * sum_c f1[b,c,y,x] * f2pad[b,c,y+di,x+dj]
// f1,f2: [4,64,192,448] f32; out: [4,81,192,448] f32; D=4.
//
// R8 champion structure (115.5us) + fp16 f2:
//  - pre-pass converts f2 -> zero-padded fp16 scratch [4][64][200][456]
//  - main kernel window loads are 12 halves (3x LDS.64, 96B-padded rows: ideal banking)
//  - f1 stays fp32; FMA loop and 4-deep cp.async ring unchanged; 16-stage full unroll.

#define D    4
#define CC   64
#define HH   192
#define WW   448
#define BB   4
#define XT   32
#define YT   4
#define XPT  4
#define NTX  8
#define NDJ  9
#define NDI  9
#define PW   (XT + 2*D)      // 40 halves of real data per row
#define PWS  48              // padded smem row (96 B) for ideal banking
#define PH   (YT + 2*D)      // 12
#define CS   4               // channels per stage
#define NSTAGE (CC / CS)     // 16
#define NTHREADS (NTX * YT * NDI)  // 288
#define RING 4

#define PH2  (HH + 2*D)      // 200
#define PW2  (WW + 2*D)      // 456 (row = 912 B, 16B-aligned)

#define F2S_BYTES  (CS*PH*PWS*2)          // 4608
#define STAGE_BYTES (F2S_BYTES + CS*YT*XT*4)  // 6656
#define STAGE_FLOATS (STAGE_BYTES/4)

#define NCH_F2 (CS*PH*(PW/8))   // 240 16B chunks (8 halves each)
#define NCH_F1 (CS*YT*(XT/4))   // 128 16B chunks (4 floats each)
#define NCH    (NCH_F2 + NCH_F1) // 368 = 288 + 80

// fp16 padded copy of f2: [B][C][PH2][PW2]
__device__ __align__(16) __half g2h[(size_t)BB * CC * PH2 * PW2];

__global__ __launch_bounds__(256)
void cvt_kernel(const float* __restrict__ f2)
{
    const int total = BB * CC * PH2 * PW2;   // 23,347,200
    int idx = blockIdx.x * 256 + threadIdx.x;
    if (idx >= total) return;
    const int px = idx % PW2;
    const int t  = idx / PW2;
    const int py = t % PH2;
    const int bc = t / PH2;
    const int gx = px - D;
    const int gy = py - D;
    float v = 0.f;
    if ((unsigned)gx < WW && (unsigned)gy < HH)
        v = f2[(size_t)bc * HH * WW + (size_t)gy * WW + gx];
    g2h[idx] = __float2half(v);
}

__device__ __forceinline__ void cp_async16(unsigned saddr, const void* gaddr) {
    asm volatile("cp.async.cg.shared.global [%0], [%1], 16;"
                 :: "r"(saddr), "l"(gaddr));
}

__global__ __launch_bounds__(NTHREADS, 3)
void corr_kernel(const float* __restrict__ f1,
                 float* __restrict__ out)
{
    __shared__ char smem[RING * STAGE_BYTES];   // 26624 B

    const int tx  = threadIdx.x;   // 0..7
    const int ty  = threadIdx.y;   // 0..3
    const int di  = threadIdx.z;   // 0..8
    const int tid = (di * YT + ty) * NTX + tx;

    const int x0 = blockIdx.x * XT;
    const int y0 = blockIdx.y * YT;
    const int b  = blockIdx.z;
    const int y  = y0 + ty;
    const int xp = tx * XPT;

    const float* f1b0 = f1 + (size_t)b * CC * HH * WW;
    const unsigned sbase = (unsigned)__cvta_generic_to_shared(smem);

    // ---- precompute cp.async chunks: chunk0 for all threads, chunk1 for tid<80
    const char* gbase[2];
    unsigned    gstr[2];
    unsigned    soff[2];
    const bool  has2 = (tid < NCH - NTHREADS);   // tid < 80
#pragma unroll
    for (int k = 0; k < 2; k++) {
        const int c = tid + k * NTHREADS;
        if (c < NCH_F2) {
            const int cc  = c / (PH * (PW/8));
            const int rem = c - cc * (PH * (PW/8));
            const int r   = rem / (PW/8);
            const int h   = rem - r * (PW/8);
            // padded scratch: px = gx + D, so gx = x0-4+8h -> px = x0+8h (16B aligned)
            gbase[k] = (const char*)g2h
                     + 2 * ((size_t)(b * CC + cc) * PH2 * PW2
                            + (size_t)(y0 + r) * PW2 + x0 + 8 * h);
            gstr[k]  = CS * PH2 * PW2 * 2;   // 729600
            soff[k]  = (cc * PH + r) * (PWS * 2) + 16 * h;
        } else {
            const int c2  = c - NCH_F2;
            const int cc  = c2 / (YT * (XT/4));
            const int rem = c2 - cc * (YT * (XT/4));
            const int r   = rem / (XT/4);
            const int h   = rem - r * (XT/4);
            gbase[k] = (const char*)(f1b0 + (size_t)cc * HH * WW
                                     + (size_t)(y0 + r) * WW + x0 + 4 * h);
            gstr[k]  = CS * HH * WW * 4;
            soff[k]  = F2S_BYTES + ((cc * YT + r) * XT + 4 * h) * 4;
        }
    }

    auto prefetch = [&](int s) {
        if (s < NSTAGE) {
            const unsigned sb = sbase + (s & (RING - 1)) * STAGE_BYTES;
            const size_t gadd = (size_t)s;
            cp_async16(sb + soff[0], gbase[0] + gadd * gstr[0]);
            if (has2) cp_async16(sb + soff[1], gbase[1] + gadd * gstr[1]);
        }
        asm volatile("cp.async.commit_group;" ::: "memory");
    };

    float acc[NDJ][XPT];
#pragma unroll
    for (int dj = 0; dj < NDJ; dj++)
#pragma unroll
        for (int xx = 0; xx < XPT; xx++) acc[dj][xx] = 0.f;

    prefetch(0);
    prefetch(1);
    prefetch(2);

#pragma unroll
    for (int s = 0; s < NSTAGE; s++) {
        asm volatile("cp.async.wait_group 2;" ::: "memory");
        __syncthreads();

        const char* stg = smem + (s & (RING - 1)) * STAGE_BYTES;

#pragma unroll
        for (int cc = 0; cc < CS; cc++) {
            const float4 v1 = *(const float4*)(stg + F2S_BYTES
                                + ((cc * YT + ty) * XT + xp) * 4);

            const __half* wrow = (const __half*)(stg + (cc * PH + ty + di) * (PWS * 2)) + xp;
            const uint2 ha = *(const uint2*)(wrow);       // halves 0..3
            const uint2 hb = *(const uint2*)(wrow + 4);   // halves 4..7
            const uint2 hc = *(const uint2*)(wrow + 8);   // halves 8..11

            float w[12];
            {
                float2 p;
                p = __half22float2(*(const __half2*)&ha.x); w[0] = p.x; w[1]  = p.y;
                p = __half22float2(*(const __half2*)&ha.y); w[2] = p.x; w[3]  = p.y;
                p = __half22float2(*(const __half2*)&hb.x); w[4] = p.x; w[5]  = p.y;
                p = __half22float2(*(const __half2*)&hb.y); w[6] = p.x; w[7]  = p.y;
                p = __half22float2(*(const __half2*)&hc.x); w[8] = p.x; w[9]  = p.y;
                p = __half22float2(*(const __half2*)&hc.y); w[10] = p.x; w[11] = p.y;
            }

#pragma unroll
            for (int dj = 0; dj < NDJ; dj++) {
                acc[dj][0] += v1.x * w[dj + 0];
                acc[dj][1] += v1.y * w[dj + 1];
                acc[dj][2] += v1.z * w[dj + 2];
                acc[dj][3] += v1.w * w[dj + 3];
            }
        }
        // Prefetch at END of compute (measured best): stage s+3 lands in buffer
        // (s-1)&3, fully consumed before this stage's barrier.
        prefetch(s + 3);
    }

    const float scale = 1.f / (float)CC;
    float* ob = out + (((size_t)b * (NDI * NDJ) + di * NDJ) * HH + y) * WW + x0 + xp;
#pragma unroll
    for (int dj = 0; dj < NDJ; dj++) {
        float4 o;
        o.x = acc[dj][0] * scale;
        o.y = acc[dj][1] * scale;
        o.z = acc[dj][2] * scale;
        o.w = acc[dj][3] * scale;
        *(float4*)&ob[(size_t)dj * HH * WW] = o;
    }
}

extern "C" void kernel_launch(void* const* d_in, const int* in_sizes, int n_in,
                              void* d_out, int out_size)
{
    const float* f1 = (const float*)d_in[0];
    const float* f2 = (const float*)d_in[1];
    float* out = (float*)d_out;

    const int total = BB * CC * PH2 * PW2;
    cvt_kernel<<<(total + 255) / 256, 256>>>(f2);

    dim3 grid(WW / XT, HH / YT, BB);   // 14 x 48 x 4 = 2688 CTAs
    dim3 block(NTX, YT, NDI);          // 288 threads
    corr_kernel<<<grid, block>>>(f1, out);
}

// round 11
// speedup vs baseline: 1.5851x; 1.5851x over previous
#include <cuda_runtime.h>
#include <cuda_fp16.h>

// Correlation as banded fp16 GEMM (HMMA, fp32 accum):
// out[b, di*9+dj, y, x] = (1/64) * sum_c f1[b,c,y,x] * f2pad[b,c,y+di,x+dj]
// For each (b,y,di): C[x, x'] = sum_c f1[c,x] * f2[c,x'];  out dj = x' - x + 4.
// CTA = (b, 4 y-rows, 32 x-pixels): m16n8k16 tiles on the 9-wide diagonal band.

#define BB 4
#define CC 64
#define HH 192
#define WW 448
#define DD 4
#define PH2 (HH + 2*DD)   // 200
#define PW2 (WW + 2*DD)   // 456

#define YTI 4
#define XTI 32
#define NTHR 256

// smem layout (bytes)
#define F1S_KSTRIDE 272                   // 4y*32x*2B + 16 pad  (16 mod 128 -> LDSM conflict-free)
#define F1S_BYTES   (CC * F1S_KSTRIDE)    // 17408
#define F2S_ROWB    96                    // 48 halves/row (40 real)
#define F2S_KSTRIDE (12*F2S_ROWB + 16)    // 1168 (16 mod 128)
#define F2S_OFF     F1S_BYTES
#define F2S_BYTES   (CC * F2S_KSTRIDE)    // 74752
#define EPI_OFF     (F2S_OFF + F2S_BYTES) // 92160
#define SMEM_TOTAL  (EPI_OFF + 9*YTI*XTI*4)  // 96768

// fp16 zero-padded copy of f2: [B][C][PH2][PW2]
__device__ __align__(16) __half f2h[(size_t)BB * CC * PH2 * PW2];

__global__ __launch_bounds__(256)
void cvt2_kernel(const float* __restrict__ f2)
{
    size_t idx = (size_t)blockIdx.x * 256 + threadIdx.x;
    const size_t total8 = (size_t)BB * CC * PH2 * PW2 / 8;
    if (idx >= total8) return;
    size_t h8 = idx * 8;
    int px = (int)(h8 % PW2);          // PW2 divisible by 8 -> no row crossing
    size_t t = h8 / PW2;
    int py = (int)(t % PH2);
    int bc = (int)(t / PH2);
    int gy = py - DD;
    const bool rowok = (unsigned)gy < HH;
    const float* src = f2 + ((size_t)bc * HH + gy) * WW;
    __half o[8];
#pragma unroll
    for (int j = 0; j < 8; j++) {
        int gx = px - DD + j;
        float v = (rowok && (unsigned)gx < WW) ? src[gx] : 0.f;
        o[j] = __float2half(v);
    }
    *(uint4*)&f2h[h8] = *(uint4*)o;
}

__global__ __launch_bounds__(NTHR, 2)
void corr_mma(const float* __restrict__ f1, float* __restrict__ out)
{
    extern __shared__ char smem[];
    const unsigned sb = (unsigned)__cvta_generic_to_shared(smem);
    const int tid  = threadIdx.x;
    const int lane = tid & 31;
    const int w    = tid >> 5;        // 8 warps
    const int yy   = w >> 1;          // warp's y row (0..3)
    const int mb   = (w & 1) * 16;    // warp's m-tile base pixel (0 or 16)
    const int b  = blockIdx.z;
    const int y0 = blockIdx.y * YTI;
    const int x0 = blockIdx.x * XTI;

    // ---- f2 tile via cp.async: 64k x 12 rows x 40 halves = 3840 16B chunks ----
    {
        const __half* f2b = f2h + (size_t)b * CC * PH2 * PW2;
#pragma unroll
        for (int i = 0; i < 15; i++) {
            int c = tid + i * 256;
            int k = c / 60, rem = c - k * 60;
            int r = rem / 5, h = rem - r * 5;
            const void* g = f2b + ((size_t)k * PH2 + y0 + r) * PW2 + x0 + h * 8;
            unsigned s = sb + F2S_OFF + k * F2S_KSTRIDE + r * F2S_ROWB + h * 16;
            asm volatile("cp.async.cg.shared.global [%0], [%1], 16;" :: "r"(s), "l"(g));
        }
        asm volatile("cp.async.commit_group;" ::: "memory");
    }

    // ---- f1 tile: LDG fp32 -> half -> STS (overlaps the cp.async) ----
    {
        const float* f1b = f1 + (size_t)b * CC * HH * WW;
#pragma unroll
        for (int i = 0; i < 8; i++) {
            int id = tid + i * 256;       // 2048 float4 chunks: 64k x 4y x 8
            int k = id >> 5, rem = id & 31;
            int ry = rem >> 3, h = rem & 7;
            float4 v = *(const float4*)(f1b + ((size_t)k * HH + y0 + ry) * WW + x0 + h * 4);
            __half2 h0 = __floats2half2_rn(v.x, v.y);
            __half2 h1 = __floats2half2_rn(v.z, v.w);
            unsigned s = sb + k * F1S_KSTRIDE + (ry * 32 + h * 4) * 2;
            asm volatile("st.shared.v2.b32 [%0], {%1,%2};"
                         :: "r"(s), "r"(*(unsigned*)&h0), "r"(*(unsigned*)&h1));
        }
    }

    asm volatile("cp.async.wait_group 0;" ::: "memory");
    __syncthreads();

    // ---- ldmatrix lane addresses (trans: smem is [k][m] / [k][n]) ----
    const int gq = lane >> 3, lr = lane & 7;
    const unsigned aAddr = sb + (((gq & 2) << 2) + lr) * F1S_KSTRIDE
                         + (yy * 32 + mb + ((gq & 1) << 3)) * 2;
    const unsigned bAddr = sb + F2S_OFF + (((gq & 1) << 3) + lr) * F2S_KSTRIDE
                         + yy * F2S_ROWB + mb * 2;

    // A fragments: loaded once, reused for all 9 di
    unsigned a[4][4];
#pragma unroll
    for (int ks = 0; ks < 4; ks++)
        asm volatile("ldmatrix.sync.aligned.m8n8.x4.trans.shared.b16 {%0,%1,%2,%3}, [%4];"
            : "=r"(a[ks][0]), "=r"(a[ks][1]), "=r"(a[ks][2]), "=r"(a[ks][3])
            : "r"(aAddr + ks * 16 * F1S_KSTRIDE));

    float* epi = (float*)(smem + EPI_OFF);
    const int g = lane >> 2, tg = lane & 3;
    const float scale = 1.f / 64.f;

    for (int di = 0; di < 9; di++) {
        float acc[3][4];
#pragma unroll
        for (int q = 0; q < 3; q++)
#pragma unroll
            for (int p = 0; p < 4; p++) acc[q][p] = 0.f;

#pragma unroll
        for (int q = 0; q < 3; q++) {
#pragma unroll
            for (int ks = 0; ks < 4; ks++) {
                unsigned b0, b1;
                asm volatile("ldmatrix.sync.aligned.m8n8.x2.trans.shared.b16 {%0,%1}, [%2];"
                    : "=r"(b0), "=r"(b1)
                    : "r"(bAddr + di * F2S_ROWB + q * 16 + ks * 16 * F2S_KSTRIDE));
                asm volatile(
                    "mma.sync.aligned.m16n8k16.row.col.f32.f16.f16.f32 "
                    "{%0,%1,%2,%3}, {%4,%5,%6,%7}, {%8,%9}, {%0,%1,%2,%3};"
                    : "+f"(acc[q][0]), "+f"(acc[q][1]), "+f"(acc[q][2]), "+f"(acc[q][3])
                    : "r"(a[ks][0]), "r"(a[ks][1]), "r"(a[ks][2]), "r"(a[ks][3]),
                      "r"(b0), "r"(b1));
            }
        }

        // band extraction: dj = n_local - m_local, keep 0..8
#pragma unroll
        for (int q = 0; q < 3; q++) {
#pragma unroll
            for (int p = 0; p < 4; p++) {
                int m  = g + ((p >> 1) << 3);
                int dj = 8 * q + 2 * tg + (p & 1) - m;
                if ((unsigned)dj <= 8u)
                    epi[(dj * YTI + yy) * XTI + mb + m] = acc[q][p];
            }
        }
        __syncthreads();

        // coalesced store of 9 x 4 x 32 floats
#pragma unroll
        for (int i = 0; i < 5; i++) {
            int idx = tid + i * 256;
            if (idx < 9 * YTI * XTI) {
                int dj  = idx / (YTI * XTI);
                int rem = idx - dj * (YTI * XTI);
                int ry = rem >> 5, xx = rem & 31;
                out[((size_t)(b * 81 + di * 9 + dj) * HH + y0 + ry) * WW + x0 + xx]
                    = epi[idx] * scale;
            }
        }
        __syncthreads();
    }
}

extern "C" void kernel_launch(void* const* d_in, const int* in_sizes, int n_in,
                              void* d_out, int out_size)
{
    const float* f1 = (const float*)d_in[0];
    const float* f2 = (const float*)d_in[1];
    float* out = (float*)d_out;

    const size_t total8 = (size_t)BB * CC * PH2 * PW2 / 8;
    cvt2_kernel<<<(unsigned)((total8 + 255) / 256), 256>>>(f2);

    cudaFuncSetAttribute(corr_mma,
                         cudaFuncAttributeMaxDynamicSharedMemorySize, SMEM_TOTAL);
    dim3 grid(WW / XTI, HH / YTI, BB);   // 14 x 48 x 4 = 2688
    corr_mma<<<grid, NTHR, SMEM_TOTAL>>>(f1, out);
}